// round 15
// baseline (speedup 1.0000x reference)
#include <cuda_runtime.h>
#include <cuda_fp16.h>
#include <math.h>

#define NMAX 100000
#define EMAX 800000
#define ETMAX (NMAX + EMAX)
#define GMAX 128

// ---------------- device scratch ----------------
__device__ __half g_H[NMAX * 256];
__device__ __half g_OUT[NMAX * 256];
__device__ __half g_H1[NMAX * 64];
__device__ __half g_H2[NMAX * 64];
__device__ float g_AS[NMAX * 4];
__device__ float g_AD[NMAX * 4];
__device__ float g_AS2[NMAX * 4];
__device__ float g_AD2[NMAX * 4];
__device__ int   g_deg[NMAX];
__device__ int   g_rowptr[NMAX + 1];
__device__ int   g_cur[NMAX];
__device__ int   g_adj[ETMAX];
__device__ int   g_bsum[256];
__device__ float g_SUMP1[GMAX * 64];
__device__ int   g_MAXP1[GMAX * 64];
__device__ int   g_CNT1[GMAX];
__device__ float g_SUMP2[GMAX * 64];
__device__ int   g_MAXP2[GMAX * 64];
__device__ int   g_CNT2[GMAX];

// ---------------- helpers ----------------
__device__ __forceinline__ int fmap(float f) {
    int i = __float_as_int(f);
    return i >= 0 ? i : (i ^ 0x7FFFFFFF);
}
__device__ __forceinline__ float funmap(int i) {
    return __int_as_float(i >= 0 ? i : (i ^ 0x7FFFFFFF));
}
__device__ __forceinline__ float selu_f(float x) {
    const float a = 1.6732632423543772f, s = 1.0507009873554805f;
    return x > 0.f ? s * x : s * a * (expf(x) - 1.f);
}
__device__ __forceinline__ void mma_f16(float& c0, float& c1, float& c2, float& c3,
                                        unsigned a0, unsigned a1, unsigned a2, unsigned a3,
                                        unsigned b0, unsigned b1) {
    asm volatile(
        "mma.sync.aligned.m16n8k16.row.col.f32.f16.f16.f32 "
        "{%0,%1,%2,%3}, {%4,%5,%6,%7}, {%8,%9}, {%0,%1,%2,%3};"
        : "+f"(c0), "+f"(c1), "+f"(c2), "+f"(c3)
        : "r"(a0), "r"(a1), "r"(a2), "r"(a3), "r"(b0), "r"(b1));
}
__device__ __forceinline__ void ldmatrix_x4(unsigned& r0, unsigned& r1,
                                            unsigned& r2, unsigned& r3,
                                            const void* smem_ptr) {
    unsigned addr = (unsigned)__cvta_generic_to_shared(smem_ptr);
    asm volatile("ldmatrix.sync.aligned.m8n8.x4.shared.b16 {%0,%1,%2,%3}, [%4];"
                 : "=r"(r0), "=r"(r1), "=r"(r2), "=r"(r3) : "r"(addr));
}

// =================== init kernels ===================
__global__ void init_csr_kernel(int* __restrict__ deg, int* __restrict__ cur, int N) {
    int i = blockIdx.x * blockDim.x + threadIdx.x;
    if (i < N) { deg[i] = 1; cur[i] = 0; }
}
__global__ void init_main_kernel(float* __restrict__ AS, float* __restrict__ AD,
                                 float* __restrict__ AS2, float* __restrict__ AD2,
                                 float* __restrict__ SUMP1, int* __restrict__ MAXP1,
                                 int* __restrict__ CNT1,
                                 float* __restrict__ SUMP2, int* __restrict__ MAXP2,
                                 int* __restrict__ CNT2, int N) {
    int i = blockIdx.x * blockDim.x + threadIdx.x;
    if (i < N * 4) { AS[i] = 0.f; AD[i] = 0.f; AS2[i] = 0.f; AD2[i] = 0.f; }
    if (i < GMAX * 64) {
        SUMP1[i] = 0.f; MAXP1[i] = fmap(-INFINITY);
        SUMP2[i] = 0.f; MAXP2[i] = fmap(-INFINITY);
    }
    if (i < GMAX) { CNT1[i] = 0; CNT2[i] = 0; }
}

// =================== CSR build ===================
__global__ void deg_count_kernel(const int* __restrict__ ei, int* __restrict__ deg, int E) {
    int e = blockIdx.x * blockDim.x + threadIdx.x;
    if (e < E) atomicAdd(&deg[ei[E + e]], 1);
}
__global__ void scan1_kernel(const int* __restrict__ deg, int* __restrict__ rowptr,
                             int* __restrict__ bsum, int N) {
    __shared__ int sh[256];
    int tid = threadIdx.x;
    int base = blockIdx.x * 2048 + tid * 8;
    int v[8], pre[8];
    int sum = 0;
    #pragma unroll
    for (int j = 0; j < 8; j++) {
        v[j] = (base + j < N) ? deg[base + j] : 0;
        pre[j] = sum;
        sum += v[j];
    }
    sh[tid] = sum;
    __syncthreads();
    for (int off = 1; off < 256; off <<= 1) {
        int t = (tid >= off) ? sh[tid - off] : 0;
        __syncthreads();
        sh[tid] += t;
        __syncthreads();
    }
    int texcl = sh[tid] - sum;
    #pragma unroll
    for (int j = 0; j < 8; j++)
        if (base + j < N) rowptr[base + j] = texcl + pre[j];
    if (tid == 255) bsum[blockIdx.x] = sh[255];
}
__global__ void scan23_kernel(int* __restrict__ rowptr, const int* __restrict__ bsum,
                              int N, int ET) {
    __shared__ int s_add;
    int tid = threadIdx.x;
    if (tid < 32) {
        int s = 0;
        for (int j = tid; j < blockIdx.x; j += 32) s += bsum[j];
        #pragma unroll
        for (int off = 16; off; off >>= 1) s += __shfl_down_sync(0xFFFFFFFFu, s, off);
        if (tid == 0) s_add = s;
    }
    __syncthreads();
    int add = s_add;
    int base = blockIdx.x * 2048 + tid * 8;
    #pragma unroll
    for (int j = 0; j < 8; j++)
        if (base + j < N) rowptr[base + j] += add;
    if (blockIdx.x == 0 && tid == 0) rowptr[N] = ET;
}
__global__ void fill_kernel(const int* __restrict__ ei, const int* __restrict__ rowptr,
                            int* __restrict__ cur, int* __restrict__ adj, int E, int ET) {
    int idx = blockIdx.x * blockDim.x + threadIdx.x;
    if (idx >= ET) return;
    int src, dst;
    if (idx < E) { src = ei[idx]; dst = ei[E + idx]; }
    else         { src = dst = idx - E; }
    adj[rowptr[dst] + atomicAdd(&cur[dst], 1)] = src;
}

// =================== fp16 m16n8k16 GEMM (ldmatrix A-frags, early prefetch) ===================
// AHALF: 0 = A fp32, 1 = A fp16
// EPI: 0 = plain fp32, 1 = bias+selu fp32, 2 = fp16 + fused att dots, 3 = bias+selu fp16
// SIDE: 0 = none; 2 = last-grid.x blocks do pool_acc (Hx fp16)
template <int BN, int WARPS_M, int WARPS_N, int EPI, int SIDE, int AHALF>
__global__ void __launch_bounds__(256)
f16_gemm_kernel(const void* __restrict__ Av, const float* __restrict__ B,
                const float* __restrict__ bias, void* __restrict__ Cv,
                const float* __restrict__ a_src, const float* __restrict__ a_dst,
                float* __restrict__ AS, float* __restrict__ AD,
                const void* sp0, const void* sp1, void* sp2, void* sp3, void* sp4,
                int M, int N, int K, int sE) {
    if (SIDE == 2 && blockIdx.x == gridDim.x - 1) {
        const __half* Hx = (const __half*)sp0;
        const int* batch = (const int*)sp1;
        float* SUMP = (float*)sp2;
        int* MAXP = (int*)sp3;
        int* CNT = (int*)sp4;
        int c = threadIdx.x & 63;
        int r = blockIdx.y * 128 + (threadIdx.x >> 6);
        int rend = blockIdx.y * 128 + 128;
        if (rend > M) rend = M;
        float sum = 0.f, mx = -INFINITY;
        int cnt = 0, curg = -1;
        for (; r < rend; r += 4) {
            int g = batch[r];
            float v = __half2float(Hx[(size_t)r * 64 + c]);
            if (g != curg) {
                if (curg >= 0) {
                    atomicAdd(&SUMP[curg * 64 + c], sum);
                    atomicMax(&MAXP[curg * 64 + c], fmap(mx));
                    if (c == 0) atomicAdd(&CNT[curg], cnt);
                }
                curg = g; sum = 0.f; mx = -INFINITY; cnt = 0;
            }
            sum += v;
            mx = fmaxf(mx, v);
            cnt++;
        }
        if (curg >= 0) {
            atomicAdd(&SUMP[curg * 64 + c], sum);
            atomicMax(&MAXP[curg * 64 + c], fmap(mx));
            if (c == 0) atomicAdd(&CNT[curg], cnt);
        }
        return;
    }

    const int WM = 128 / WARPS_M, WN = BN / WARPS_N;
    const int MT = WM / 16, NT = WN / 8;
    const int ASTR = 24;
    __shared__ __half  Asm[2][128][ASTR];
    __shared__ __half2 Bs2[2][8][BN + 8];

    int tid = threadIdx.x;
    int warp = tid >> 5, lane = tid & 31;
    int lr = lane >> 2, lc = lane & 3;
    int warp_m = warp / WARPS_N, warp_n = warp % WARPS_N;
    int wm0 = warp_m * WM, wn0 = warp_n * WN;
    int m0 = blockIdx.y * 128, n0 = blockIdx.x * BN;

    int lm_row = lane & 15;
    int lm_col = (lane < 16) ? 0 : 8;

    float c[MT][NT][4];
    #pragma unroll
    for (int i = 0; i < MT; i++)
        #pragma unroll
        for (int j = 0; j < NT; j++)
            #pragma unroll
            for (int q = 0; q < 4; q++) c[i][j][q] = 0.f;

    const float* Af = (const float*)Av;
    const __half* Ah = (const __half*)Av;
    float4 areg[2];
    uint4 ahreg;
    float4 bga, bgb;
    const int BTASK = 8 * (BN / 4);
    int bk2 = tid / (BN / 4);
    int bnc = (tid % (BN / 4)) * 4;

    auto ldA = [&](int k0) {
        if (AHALF) {
            int gm = m0 + (tid >> 1), gk = k0 + (tid & 1) * 8;
            uint4 z = {0u, 0u, 0u, 0u};
            ahreg = (gm < M && gk < K) ? *(const uint4*)&Ah[(size_t)gm * K + gk] : z;
        } else {
            #pragma unroll
            for (int q = 0; q < 2; q++) {
                int f = tid + q * 256;
                int r = f >> 2, cc = (f & 3) * 4;
                int gm = m0 + r, gk = k0 + cc;
                float4 v = {0.f, 0.f, 0.f, 0.f};
                if (gm < M && gk < K) v = *(const float4*)&Af[(size_t)gm * K + gk];
                areg[q] = v;
            }
        }
    };
    auto stA = [&](int buf) {
        if (AHALF) {
            int r = tid >> 1, cc = (tid & 1) * 8;
            *(__half2*)&Asm[buf][r][cc + 0] = *(const __half2*)&ahreg.x;
            *(__half2*)&Asm[buf][r][cc + 2] = *(const __half2*)&ahreg.y;
            *(__half2*)&Asm[buf][r][cc + 4] = *(const __half2*)&ahreg.z;
            *(__half2*)&Asm[buf][r][cc + 6] = *(const __half2*)&ahreg.w;
        } else {
            #pragma unroll
            for (int q = 0; q < 2; q++) {
                int f = tid + q * 256;
                int r = f >> 2, cc = (f & 3) * 4;
                *(__half2*)&Asm[buf][r][cc]     = __floats2half2_rn(areg[q].x, areg[q].y);
                *(__half2*)&Asm[buf][r][cc + 2] = __floats2half2_rn(areg[q].z, areg[q].w);
            }
        }
    };
    auto ldB = [&](int k0) {
        if (tid < BTASK) {
            int gk0 = k0 + 2 * bk2, gk1 = gk0 + 1;
            float4 z = {0.f, 0.f, 0.f, 0.f};
            bga = (gk0 < K) ? *(const float4*)&B[(size_t)gk0 * N + n0 + bnc] : z;
            bgb = (gk1 < K) ? *(const float4*)&B[(size_t)gk1 * N + n0 + bnc] : z;
        }
    };
    auto stB = [&](int buf) {
        if (tid < BTASK) {
            Bs2[buf][bk2][bnc + 0] = __floats2half2_rn(bga.x, bgb.x);
            Bs2[buf][bk2][bnc + 1] = __floats2half2_rn(bga.y, bgb.y);
            Bs2[buf][bk2][bnc + 2] = __floats2half2_rn(bga.z, bgb.z);
            Bs2[buf][bk2][bnc + 3] = __floats2half2_rn(bga.w, bgb.w);
        }
    };

    int nk = (K + 15) / 16;
    ldA(0);
    ldB(0);
    for (int t = 0; t < nk; t++) {
        int buf = t & 1;
        stA(buf);
        stB(buf);
        if (t + 1 < nk) { ldA((t + 1) * 16); ldB((t + 1) * 16); }
        __syncthreads();

        unsigned af[MT][4];
        #pragma unroll
        for (int mt = 0; mt < MT; mt++)
            ldmatrix_x4(af[mt][0], af[mt][1], af[mt][2], af[mt][3],
                        &Asm[buf][wm0 + mt * 16 + lm_row][lm_col]);
        unsigned bf[NT][2];
        #pragma unroll
        for (int nt = 0; nt < NT; nt++) {
            int n = wn0 + nt * 8 + lr;
            bf[nt][0] = *(const unsigned*)&Bs2[buf][lc][n];
            bf[nt][1] = *(const unsigned*)&Bs2[buf][lc + 4][n];
        }
        #pragma unroll
        for (int mt = 0; mt < MT; mt++)
            #pragma unroll
            for (int nt = 0; nt < NT; nt++)
                mma_f16(c[mt][nt][0], c[mt][nt][1], c[mt][nt][2], c[mt][nt][3],
                        af[mt][0], af[mt][1], af[mt][2], af[mt][3],
                        bf[nt][0], bf[nt][1]);
    }

    // ---- epilogue ----
    float asv[NT][2], adv[NT][2];
    if (EPI == 2) {
        #pragma unroll
        for (int nt = 0; nt < NT; nt++) {
            int gc = n0 + wn0 + nt * 8 + lc * 2;
            asv[nt][0] = a_src[gc]; asv[nt][1] = a_src[gc + 1];
            adv[nt][0] = a_dst[gc]; adv[nt][1] = a_dst[gc + 1];
        }
    }
    float* Cf = (float*)Cv;
    __half* Ch = (__half*)Cv;
    #pragma unroll
    for (int mt = 0; mt < MT; mt++) {
        int r0 = m0 + wm0 + mt * 16 + lr;
        int r1 = r0 + 8;
        float s0 = 0.f, s1 = 0.f, d0 = 0.f, d1 = 0.f;
        #pragma unroll
        for (int nt = 0; nt < NT; nt++) {
            int gc = n0 + wn0 + nt * 8 + lc * 2;
            float v0 = c[mt][nt][0], v1 = c[mt][nt][1];
            float v2 = c[mt][nt][2], v3 = c[mt][nt][3];
            if (EPI == 1 || EPI == 3) {
                float b0 = bias[gc], b1 = bias[gc + 1];
                v0 = selu_f(v0 + b0); v1 = selu_f(v1 + b1);
                v2 = selu_f(v2 + b0); v3 = selu_f(v3 + b1);
            }
            if (EPI == 2) {
                s0 += v0 * asv[nt][0] + v1 * asv[nt][1];
                s1 += v2 * asv[nt][0] + v3 * asv[nt][1];
                d0 += v0 * adv[nt][0] + v1 * adv[nt][1];
                d1 += v2 * adv[nt][0] + v3 * adv[nt][1];
            }
            if (EPI == 2 || EPI == 3) {
                if (r0 < M) *(__half2*)&Ch[(size_t)r0 * N + gc] = __floats2half2_rn(v0, v1);
                if (r1 < M) *(__half2*)&Ch[(size_t)r1 * N + gc] = __floats2half2_rn(v2, v3);
            } else {
                if (r0 < M) *(float2*)&Cf[(size_t)r0 * N + gc] = make_float2(v0, v1);
                if (r1 < M) *(float2*)&Cf[(size_t)r1 * N + gc] = make_float2(v2, v3);
            }
        }
        if (EPI == 2) {
            s0 += __shfl_xor_sync(0xFFFFFFFFu, s0, 1);
            s0 += __shfl_xor_sync(0xFFFFFFFFu, s0, 2);
            s1 += __shfl_xor_sync(0xFFFFFFFFu, s1, 1);
            s1 += __shfl_xor_sync(0xFFFFFFFFu, s1, 2);
            d0 += __shfl_xor_sync(0xFFFFFFFFu, d0, 1);
            d0 += __shfl_xor_sync(0xFFFFFFFFu, d0, 2);
            d1 += __shfl_xor_sync(0xFFFFFFFFu, d1, 1);
            d1 += __shfl_xor_sync(0xFFFFFFFFu, d1, 2);
            if (lc == 0) {
                int h = (n0 + wn0) >> 6;
                if (r0 < M) { atomicAdd(&AS[r0 * 4 + h], s0); atomicAdd(&AD[r0 * 4 + h], d0); }
                if (r1 < M) { atomicAdd(&AS[r1 * 4 + h], s1); atomicAdd(&AD[r1 * 4 + h], d1); }
            }
        }
    }
}

// =================== GAT gather: 2 warps per dst (half row each), 4-edge unroll ===================
__device__ __forceinline__ void ons_update4(float e, const float* v,
                                            float& m, float& s, float* acc) {
    if (e <= m) {
        float w = expf(e - m);
        s += w;
        #pragma unroll
        for (int q = 0; q < 4; q++) acc[q] += w * v[q];
    } else {
        float sc = expf(m - e);
        s = s * sc + 1.f;
        #pragma unroll
        for (int q = 0; q < 4; q++) acc[q] = acc[q] * sc + v[q];
        m = e;
    }
}
__device__ __forceinline__ void unpack4(uint2 u, float* v) {
    float2 f0 = __half22float2(*(const __half2*)&u.x);
    float2 f1 = __half22float2(*(const __half2*)&u.y);
    v[0] = f0.x; v[1] = f0.y; v[2] = f1.x; v[3] = f1.y;
}

__global__ void gat_gather_kernel(const int* __restrict__ rowptr, const int* __restrict__ adj,
                                  const __half* __restrict__ H, const float* __restrict__ AS,
                                  const float* __restrict__ AD, const float* __restrict__ gb,
                                  __half* __restrict__ OUT, int N) {
    int gwh = (blockIdx.x * blockDim.x + threadIdx.x) >> 5;   // N*2 warp-halves
    int lane = threadIdx.x & 31;
    int dst = gwh >> 1;
    if (dst >= N) return;
    int half = gwh & 1;                   // which 128-col half of the row
    int h = half * 2 + (lane >> 4);       // head: cols (half*128 + lane*4)>>6
    float adh = AD[dst * 4 + h];
    int beg = rowptr[dst], end = rowptr[dst + 1];
    int coff = half * 128 + lane * 4;     // column offset in halves
    float acc[4] = {};
    float m = -INFINITY, s = 0.f;
    int i = beg;
    for (; i + 4 <= end; i += 4) {
        int s0 = adj[i], s1 = adj[i + 1], s2 = adj[i + 2], s3 = adj[i + 3];
        float e0 = AS[s0 * 4 + h], e1 = AS[s1 * 4 + h];
        float e2 = AS[s2 * 4 + h], e3 = AS[s3 * 4 + h];
        uint2 u0 = *(const uint2*)(H + (size_t)s0 * 256 + coff);
        uint2 u1 = *(const uint2*)(H + (size_t)s1 * 256 + coff);
        uint2 u2 = *(const uint2*)(H + (size_t)s2 * 256 + coff);
        uint2 u3 = *(const uint2*)(H + (size_t)s3 * 256 + coff);
        e0 += adh; e1 += adh; e2 += adh; e3 += adh;
        e0 = e0 > 0.f ? e0 : 0.2f * e0;
        e1 = e1 > 0.f ? e1 : 0.2f * e1;
        e2 = e2 > 0.f ? e2 : 0.2f * e2;
        e3 = e3 > 0.f ? e3 : 0.2f * e3;
        float v[4];
        unpack4(u0, v); ons_update4(e0, v, m, s, acc);
        unpack4(u1, v); ons_update4(e1, v, m, s, acc);
        unpack4(u2, v); ons_update4(e2, v, m, s, acc);
        unpack4(u3, v); ons_update4(e3, v, m, s, acc);
    }
    for (; i < end; i++) {
        int s0 = adj[i];
        float e0 = AS[s0 * 4 + h] + adh;
        uint2 u0 = *(const uint2*)(H + (size_t)s0 * 256 + coff);
        float v[4];
        unpack4(u0, v);
        e0 = e0 > 0.f ? e0 : 0.2f * e0;
        ons_update4(e0, v, m, s, acc);
    }
    float inv = 1.f / (s + 1e-16f);
    const float* gbp = gb + coff;
    uint2 o;
    *(__half2*)&o.x = __floats2half2_rn(acc[0] * inv + gbp[0], acc[1] * inv + gbp[1]);
    *(__half2*)&o.y = __floats2half2_rn(acc[2] * inv + gbp[2], acc[3] * inv + gbp[3]);
    *(uint2*)(OUT + (size_t)dst * 256 + coff) = o;
}

// =================== standalone pool acc (fp16 input) ===================
__global__ void pool_acc_kernel(const __half* __restrict__ Hx, const int* __restrict__ batch,
                                float* __restrict__ SUMP, int* __restrict__ MAXP,
                                int* __restrict__ CNT, int N) {
    int c = threadIdx.x & 63;
    int r = blockIdx.x * 128 + (threadIdx.x >> 6);
    int rend = blockIdx.x * 128 + 128;
    if (rend > N) rend = N;
    float sum = 0.f, mx = -INFINITY;
    int cnt = 0, curg = -1;
    for (; r < rend; r += 4) {
        int g = batch[r];
        float v = __half2float(Hx[(size_t)r * 64 + c]);
        if (g != curg) {
            if (curg >= 0) {
                atomicAdd(&SUMP[curg * 64 + c], sum);
                atomicMax(&MAXP[curg * 64 + c], fmap(mx));
                if (c == 0) atomicAdd(&CNT[curg], cnt);
            }
            curg = g; sum = 0.f; mx = -INFINITY; cnt = 0;
        }
        sum += v;
        mx = fmaxf(mx, v);
        cnt++;
    }
    if (curg >= 0) {
        atomicAdd(&SUMP[curg * 64 + c], sum);
        atomicMax(&MAXP[curg * 64 + c], fmap(mx));
        if (c == 0) atomicAdd(&CNT[curg], cnt);
    }
}

// =================== final MLP head (pool_fin fused in) ===================
__global__ void mlp_kernel(const float* __restrict__ SUMP1, const int* __restrict__ MAXP1,
                           const int* __restrict__ CNT1,
                           const float* __restrict__ SUMP2, const int* __restrict__ MAXP2,
                           const int* __restrict__ CNT2,
                           const float* __restrict__ sum_w, const float* __restrict__ sum_b,
                           const float* __restrict__ sh1_w, const float* __restrict__ sh1_b,
                           const float* __restrict__ sh2_w, const float* __restrict__ sh2_b,
                           const float* __restrict__ sh3_w, const float* __restrict__ sh3_b,
                           const float* __restrict__ reg_w, const float* __restrict__ reg_b,
                           float* __restrict__ out) {
    __shared__ float zin[256], z1[128], z2[64], z3[64];
    int g = blockIdx.x, t = threadIdx.x;  // 128 threads
    if (t < 64) {
        float c1 = (float)CNT1[g]; if (c1 < 1.f) c1 = 1.f;
        float c2 = (float)CNT2[g]; if (c2 < 1.f) c2 = 1.f;
        zin[t]        = SUMP1[g * 64 + t] / c1;
        zin[64 + t]   = funmap(MAXP1[g * 64 + t]);
        zin[128 + t]  = SUMP2[g * 64 + t] / c2;
        zin[192 + t]  = funmap(MAXP2[g * 64 + t]);
    }
    __syncthreads();
    {
        float acc = sum_b[t];
        for (int k = 0; k < 256; k++) acc += zin[k] * sum_w[k * 128 + t];
        z1[t] = acc;
    }
    __syncthreads();
    if (t < 64) {
        float acc = sh1_b[t];
        for (int k = 0; k < 128; k++) acc += z1[k] * sh1_w[k * 64 + t];
        z2[t] = selu_f(acc);
    }
    __syncthreads();
    if (t < 64) {
        float acc = sh2_b[t];
        for (int k = 0; k < 64; k++) acc += z2[k] * sh2_w[k * 64 + t];
        z3[t] = selu_f(acc);
    }
    __syncthreads();
    if (t < 64) {
        float acc = sh3_b[t];
        for (int k = 0; k < 64; k++) acc += z3[k] * sh3_w[k * 64 + t];
        z2[t] = selu_f(acc);
    }
    __syncthreads();
    if (t < 32) {
        float acc = reg_b[t];
        for (int k = 0; k < 64; k++) acc += z2[k] * reg_w[k * 32 + t];
        out[g * 32 + t] = acc;
    }
}

// =================== host orchestration ===================
extern "C" void kernel_launch(void* const* d_in, const int* in_sizes, int n_in,
                              void* d_out, int out_size) {
    const float* x       = (const float*)d_in[0];
    const int*   ei      = (const int*)d_in[1];
    const int*   batch   = (const int*)d_in[2];
    const float* gat1_w  = (const float*)d_in[3];
    const float* gat1_as = (const float*)d_in[4];
    const float* gat1_ad = (const float*)d_in[5];
    const float* gat1_b  = (const float*)d_in[6];
    const float* lin1_w  = (const float*)d_in[7];
    const float* lin1_b  = (const float*)d_in[8];
    const float* gat2_w  = (const float*)d_in[9];
    const float* gat2_as = (const float*)d_in[10];
    const float* gat2_ad = (const float*)d_in[11];
    const float* gat2_b  = (const float*)d_in[12];
    const float* lin2_w  = (const float*)d_in[13];
    const float* lin2_b  = (const float*)d_in[14];
    const float* sum_w   = (const float*)d_in[15];
    const float* sum_b   = (const float*)d_in[16];
    const float* sh1_w   = (const float*)d_in[17];
    const float* sh1_b   = (const float*)d_in[18];
    const float* sh2_w   = (const float*)d_in[19];
    const float* sh2_b   = (const float*)d_in[20];
    const float* sh3_w   = (const float*)d_in[21];
    const float* sh3_b   = (const float*)d_in[22];
    const float* reg_w   = (const float*)d_in[23];
    const float* reg_b   = (const float*)d_in[24];

    int N  = in_sizes[2];
    int E  = in_sizes[1] / 2;
    int K1 = in_sizes[0] / N;
    int ET = E + N;

    __half *H, *OUT, *H1, *H2;
    float *AS, *AD, *AS2, *AD2, *SUMP1, *SUMP2;
    int *deg, *rowptr, *cur, *adj, *bsum, *MAXP1, *CNT1, *MAXP2, *CNT2;
    cudaGetSymbolAddress((void**)&H, g_H);
    cudaGetSymbolAddress((void**)&OUT, g_OUT);
    cudaGetSymbolAddress((void**)&H1, g_H1);
    cudaGetSymbolAddress((void**)&H2, g_H2);
    cudaGetSymbolAddress((void**)&AS, g_AS);
    cudaGetSymbolAddress((void**)&AD, g_AD);
    cudaGetSymbolAddress((void**)&AS2, g_AS2);
    cudaGetSymbolAddress((void**)&AD2, g_AD2);
    cudaGetSymbolAddress((void**)&deg, g_deg);
    cudaGetSymbolAddress((void**)&rowptr, g_rowptr);
    cudaGetSymbolAddress((void**)&cur, g_cur);
    cudaGetSymbolAddress((void**)&adj, g_adj);
    cudaGetSymbolAddress((void**)&bsum, g_bsum);
    cudaGetSymbolAddress((void**)&SUMP1, g_SUMP1);
    cudaGetSymbolAddress((void**)&MAXP1, g_MAXP1);
    cudaGetSymbolAddress((void**)&CNT1, g_CNT1);
    cudaGetSymbolAddress((void**)&SUMP2, g_SUMP2);
    cudaGetSymbolAddress((void**)&MAXP2, g_MAXP2);
    cudaGetSymbolAddress((void**)&CNT2, g_CNT2);

    int nScanBlocks = (N + 2047) / 2048;
    int nyH = (N + 127) / 128;
    dim3 gH(2, nyH);
    dim3 gH2(3, nyH);
    dim3 gL(1, nyH);

    cudaStream_t s1;
    cudaStreamCreateWithFlags(&s1, cudaStreamNonBlocking);
    cudaEvent_t evFork, evCSR;
    cudaEventCreateWithFlags(&evFork, cudaEventDisableTiming);
    cudaEventCreateWithFlags(&evCSR, cudaEventDisableTiming);

    cudaEventRecord(evFork, 0);
    cudaStreamWaitEvent(s1, evFork, 0);

    // --- CSR branch (s1) ---
    init_csr_kernel<<<(N + 255) / 256, 256, 0, s1>>>(deg, cur, N);
    deg_count_kernel<<<(E + 255) / 256, 256, 0, s1>>>(ei, deg, E);
    scan1_kernel<<<nScanBlocks, 256, 0, s1>>>(deg, rowptr, bsum, N);
    scan23_kernel<<<nScanBlocks, 256, 0, s1>>>(rowptr, bsum, N, ET);
    fill_kernel<<<(ET + 255) / 256, 256, 0, s1>>>(ei, rowptr, cur, adj, E, ET);
    cudaEventRecord(evCSR, s1);

    // --- main branch ---
    init_main_kernel<<<(N * 4 + 255) / 256, 256>>>(AS, AD, AS2, AD2,
                                                   SUMP1, MAXP1, CNT1, SUMP2, MAXP2, CNT2, N);
    f16_gemm_kernel<128, 2, 4, 2, 0, 0><<<gH, 256>>>(
        x, gat1_w, nullptr, H, gat1_as, gat1_ad, AS, AD,
        nullptr, nullptr, nullptr, nullptr, nullptr, N, 256, K1, 0);

    cudaStreamWaitEvent(0, evCSR, 0);

    gat_gather_kernel<<<(N * 64 + 255) / 256, 256>>>(rowptr, adj, H, AS, AD, gat1_b, OUT, N);
    f16_gemm_kernel<64, 4, 2, 3, 0, 1><<<gL, 256>>>(
        OUT, lin1_w, lin1_b, H1, nullptr, nullptr, nullptr, nullptr,
        nullptr, nullptr, nullptr, nullptr, nullptr, N, 64, 256, 0);

    f16_gemm_kernel<128, 2, 4, 2, 2, 1><<<gH2, 256>>>(
        H1, gat2_w, nullptr, H, gat2_as, gat2_ad, AS2, AD2,
        H1, batch, SUMP1, MAXP1, CNT1, N, 256, 64, 0);

    gat_gather_kernel<<<(N * 64 + 255) / 256, 256>>>(rowptr, adj, H, AS2, AD2, gat2_b, OUT, N);
    f16_gemm_kernel<64, 4, 2, 3, 0, 1><<<gL, 256>>>(
        OUT, lin2_w, lin2_b, H2, nullptr, nullptr, nullptr, nullptr,
        nullptr, nullptr, nullptr, nullptr, nullptr, N, 64, 256, 0);

    pool_acc_kernel<<<nyH, 256>>>(H2, batch, SUMP2, MAXP2, CNT2, N);

    mlp_kernel<<<GMAX, 128>>>(SUMP1, MAXP1, CNT1, SUMP2, MAXP2, CNT2,
                              sum_w, sum_b, sh1_w, sh1_b, sh2_w, sh2_b,
                              sh3_w, sh3_b, reg_w, reg_b, (float*)d_out);
}

// round 16
// speedup vs baseline: 1.1471x; 1.1471x over previous
#include <cuda_runtime.h>
#include <cuda_fp16.h>
#include <math.h>

#define NMAX 100000
#define EMAX 800000
#define ETMAX (NMAX + EMAX)
#define GMAX 128

// ---------------- device scratch ----------------
__device__ __half g_H[NMAX * 256];
__device__ __half g_OUT[NMAX * 256];
__device__ __half g_H1[NMAX * 64];
__device__ __half g_H2[NMAX * 64];
__device__ float g_AS[NMAX * 4];
__device__ float g_AD[NMAX * 4];
__device__ float g_AS2[NMAX * 4];
__device__ float g_AD2[NMAX * 4];
__device__ int   g_deg[NMAX];
__device__ int   g_rowptr[NMAX + 1];
__device__ int   g_cur[NMAX];
__device__ int   g_adj[ETMAX];
__device__ int   g_bsum[256];
__device__ float g_SUMP1[GMAX * 64];
__device__ int   g_MAXP1[GMAX * 64];
__device__ int   g_CNT1[GMAX];
__device__ float g_SUMP2[GMAX * 64];
__device__ int   g_MAXP2[GMAX * 64];
__device__ int   g_CNT2[GMAX];

// ---------------- helpers ----------------
__device__ __forceinline__ int fmap(float f) {
    int i = __float_as_int(f);
    return i >= 0 ? i : (i ^ 0x7FFFFFFF);
}
__device__ __forceinline__ float funmap(int i) {
    return __int_as_float(i >= 0 ? i : (i ^ 0x7FFFFFFF));
}
__device__ __forceinline__ float selu_f(float x) {
    const float a = 1.6732632423543772f, s = 1.0507009873554805f;
    return x > 0.f ? s * x : s * a * (expf(x) - 1.f);
}
__device__ __forceinline__ void mma_f16(float& c0, float& c1, float& c2, float& c3,
                                        unsigned a0, unsigned a1, unsigned a2, unsigned a3,
                                        unsigned b0, unsigned b1) {
    asm volatile(
        "mma.sync.aligned.m16n8k16.row.col.f32.f16.f16.f32 "
        "{%0,%1,%2,%3}, {%4,%5,%6,%7}, {%8,%9}, {%0,%1,%2,%3};"
        : "+f"(c0), "+f"(c1), "+f"(c2), "+f"(c3)
        : "r"(a0), "r"(a1), "r"(a2), "r"(a3), "r"(b0), "r"(b1));
}
__device__ __forceinline__ void ldmatrix_x4(unsigned& r0, unsigned& r1,
                                            unsigned& r2, unsigned& r3,
                                            const void* smem_ptr) {
    unsigned addr = (unsigned)__cvta_generic_to_shared(smem_ptr);
    asm volatile("ldmatrix.sync.aligned.m8n8.x4.shared.b16 {%0,%1,%2,%3}, [%4];"
                 : "=r"(r0), "=r"(r1), "=r"(r2), "=r"(r3) : "r"(addr));
}

// =================== init kernels ===================
__global__ void init_csr_kernel(int* __restrict__ deg, int* __restrict__ cur,
                                float* __restrict__ AS2, float* __restrict__ AD2,
                                float* __restrict__ SUMP1, int* __restrict__ MAXP1,
                                int* __restrict__ CNT1,
                                float* __restrict__ SUMP2, int* __restrict__ MAXP2,
                                int* __restrict__ CNT2, int N) {
    int i = blockIdx.x * blockDim.x + threadIdx.x;
    if (i < N) { deg[i] = 1; cur[i] = 0; }
    if (i < N * 4) { AS2[i] = 0.f; AD2[i] = 0.f; }
    if (i < GMAX * 64) {
        SUMP1[i] = 0.f; MAXP1[i] = fmap(-INFINITY);
        SUMP2[i] = 0.f; MAXP2[i] = fmap(-INFINITY);
    }
    if (i < GMAX) { CNT1[i] = 0; CNT2[i] = 0; }
}
__global__ void init_main_kernel(float* __restrict__ AS, float* __restrict__ AD, int N) {
    int i = blockIdx.x * blockDim.x + threadIdx.x;
    if (i < N * 4) { AS[i] = 0.f; AD[i] = 0.f; }
}

// =================== CSR build ===================
__global__ void deg_count_kernel(const int* __restrict__ ei, int* __restrict__ deg, int E) {
    int e = blockIdx.x * blockDim.x + threadIdx.x;
    if (e < E) atomicAdd(&deg[ei[E + e]], 1);
}
__global__ void scan1_kernel(const int* __restrict__ deg, int* __restrict__ rowptr,
                             int* __restrict__ bsum, int N) {
    __shared__ int sh[256];
    int tid = threadIdx.x;
    int base = blockIdx.x * 2048 + tid * 8;
    int v[8], pre[8];
    int sum = 0;
    #pragma unroll
    for (int j = 0; j < 8; j++) {
        v[j] = (base + j < N) ? deg[base + j] : 0;
        pre[j] = sum;
        sum += v[j];
    }
    sh[tid] = sum;
    __syncthreads();
    for (int off = 1; off < 256; off <<= 1) {
        int t = (tid >= off) ? sh[tid - off] : 0;
        __syncthreads();
        sh[tid] += t;
        __syncthreads();
    }
    int texcl = sh[tid] - sum;
    #pragma unroll
    for (int j = 0; j < 8; j++)
        if (base + j < N) rowptr[base + j] = texcl + pre[j];
    if (tid == 255) bsum[blockIdx.x] = sh[255];
}
__global__ void scan23_kernel(int* __restrict__ rowptr, const int* __restrict__ bsum,
                              int N, int ET) {
    __shared__ int s_add;
    int tid = threadIdx.x;
    if (tid < 32) {
        int s = 0;
        for (int j = tid; j < blockIdx.x; j += 32) s += bsum[j];
        #pragma unroll
        for (int off = 16; off; off >>= 1) s += __shfl_down_sync(0xFFFFFFFFu, s, off);
        if (tid == 0) s_add = s;
    }
    __syncthreads();
    int add = s_add;
    int base = blockIdx.x * 2048 + tid * 8;
    #pragma unroll
    for (int j = 0; j < 8; j++)
        if (base + j < N) rowptr[base + j] += add;
    if (blockIdx.x == 0 && tid == 0) rowptr[N] = ET;
}
__global__ void fill_kernel(const int* __restrict__ ei, const int* __restrict__ rowptr,
                            int* __restrict__ cur, int* __restrict__ adj, int E, int ET) {
    int idx = blockIdx.x * blockDim.x + threadIdx.x;
    if (idx >= ET) return;
    int src, dst;
    if (idx < E) { src = ei[idx]; dst = ei[E + idx]; }
    else         { src = dst = idx - E; }
    adj[rowptr[dst] + atomicAdd(&cur[dst], 1)] = src;
}

// =================== fp16 m16n8k16 GEMM (ldmatrix A-frags, early prefetch) ===================
// AHALF: 0 = A fp32, 1 = A fp16
// EPI: 0 = plain fp32, 1 = bias+selu fp32, 2 = fp16 + fused att dots, 3 = bias+selu fp16
// SIDE: 0 = none; 2 = last-grid.x blocks do pool_acc (Hx fp16)
template <int BN, int WARPS_M, int WARPS_N, int EPI, int SIDE, int AHALF>
__global__ void __launch_bounds__(256)
f16_gemm_kernel(const void* __restrict__ Av, const float* __restrict__ B,
                const float* __restrict__ bias, void* __restrict__ Cv,
                const float* __restrict__ a_src, const float* __restrict__ a_dst,
                float* __restrict__ AS, float* __restrict__ AD,
                const void* sp0, const void* sp1, void* sp2, void* sp3, void* sp4,
                int M, int N, int K, int sE) {
    if (SIDE == 2 && blockIdx.x == gridDim.x - 1) {
        const __half* Hx = (const __half*)sp0;
        const int* batch = (const int*)sp1;
        float* SUMP = (float*)sp2;
        int* MAXP = (int*)sp3;
        int* CNT = (int*)sp4;
        int c = threadIdx.x & 63;
        int r = blockIdx.y * 128 + (threadIdx.x >> 6);
        int rend = blockIdx.y * 128 + 128;
        if (rend > M) rend = M;
        float sum = 0.f, mx = -INFINITY;
        int cnt = 0, curg = -1;
        for (; r < rend; r += 4) {
            int g = batch[r];
            float v = __half2float(Hx[(size_t)r * 64 + c]);
            if (g != curg) {
                if (curg >= 0) {
                    atomicAdd(&SUMP[curg * 64 + c], sum);
                    atomicMax(&MAXP[curg * 64 + c], fmap(mx));
                    if (c == 0) atomicAdd(&CNT[curg], cnt);
                }
                curg = g; sum = 0.f; mx = -INFINITY; cnt = 0;
            }
            sum += v;
            mx = fmaxf(mx, v);
            cnt++;
        }
        if (curg >= 0) {
            atomicAdd(&SUMP[curg * 64 + c], sum);
            atomicMax(&MAXP[curg * 64 + c], fmap(mx));
            if (c == 0) atomicAdd(&CNT[curg], cnt);
        }
        return;
    }

    const int WM = 128 / WARPS_M, WN = BN / WARPS_N;
    const int MT = WM / 16, NT = WN / 8;
    const int ASTR = 24;
    __shared__ __half  Asm[2][128][ASTR];
    __shared__ __half2 Bs2[2][8][BN + 8];

    int tid = threadIdx.x;
    int warp = tid >> 5, lane = tid & 31;
    int lr = lane >> 2, lc = lane & 3;
    int warp_m = warp / WARPS_N, warp_n = warp % WARPS_N;
    int wm0 = warp_m * WM, wn0 = warp_n * WN;
    int m0 = blockIdx.y * 128, n0 = blockIdx.x * BN;

    int lm_row = lane & 15;
    int lm_col = (lane < 16) ? 0 : 8;

    float c[MT][NT][4];
    #pragma unroll
    for (int i = 0; i < MT; i++)
        #pragma unroll
        for (int j = 0; j < NT; j++)
            #pragma unroll
            for (int q = 0; q < 4; q++) c[i][j][q] = 0.f;

    const float* Af = (const float*)Av;
    const __half* Ah = (const __half*)Av;
    float4 areg[2];
    uint4 ahreg;
    float4 bga, bgb;
    const int BTASK = 8 * (BN / 4);
    int bk2 = tid / (BN / 4);
    int bnc = (tid % (BN / 4)) * 4;

    auto ldA = [&](int k0) {
        if (AHALF) {
            int gm = m0 + (tid >> 1), gk = k0 + (tid & 1) * 8;
            uint4 z = {0u, 0u, 0u, 0u};
            ahreg = (gm < M && gk < K) ? *(const uint4*)&Ah[(size_t)gm * K + gk] : z;
        } else {
            #pragma unroll
            for (int q = 0; q < 2; q++) {
                int f = tid + q * 256;
                int r = f >> 2, cc = (f & 3) * 4;
                int gm = m0 + r, gk = k0 + cc;
                float4 v = {0.f, 0.f, 0.f, 0.f};
                if (gm < M && gk < K) v = *(const float4*)&Af[(size_t)gm * K + gk];
                areg[q] = v;
            }
        }
    };
    auto stA = [&](int buf) {
        if (AHALF) {
            int r = tid >> 1, cc = (tid & 1) * 8;
            *(__half2*)&Asm[buf][r][cc + 0] = *(const __half2*)&ahreg.x;
            *(__half2*)&Asm[buf][r][cc + 2] = *(const __half2*)&ahreg.y;
            *(__half2*)&Asm[buf][r][cc + 4] = *(const __half2*)&ahreg.z;
            *(__half2*)&Asm[buf][r][cc + 6] = *(const __half2*)&ahreg.w;
        } else {
            #pragma unroll
            for (int q = 0; q < 2; q++) {
                int f = tid + q * 256;
                int r = f >> 2, cc = (f & 3) * 4;
                *(__half2*)&Asm[buf][r][cc]     = __floats2half2_rn(areg[q].x, areg[q].y);
                *(__half2*)&Asm[buf][r][cc + 2] = __floats2half2_rn(areg[q].z, areg[q].w);
            }
        }
    };
    auto ldB = [&](int k0) {
        if (tid < BTASK) {
            int gk0 = k0 + 2 * bk2, gk1 = gk0 + 1;
            float4 z = {0.f, 0.f, 0.f, 0.f};
            bga = (gk0 < K) ? *(const float4*)&B[(size_t)gk0 * N + n0 + bnc] : z;
            bgb = (gk1 < K) ? *(const float4*)&B[(size_t)gk1 * N + n0 + bnc] : z;
        }
    };
    auto stB = [&](int buf) {
        if (tid < BTASK) {
            Bs2[buf][bk2][bnc + 0] = __floats2half2_rn(bga.x, bgb.x);
            Bs2[buf][bk2][bnc + 1] = __floats2half2_rn(bga.y, bgb.y);
            Bs2[buf][bk2][bnc + 2] = __floats2half2_rn(bga.z, bgb.z);
            Bs2[buf][bk2][bnc + 3] = __floats2half2_rn(bga.w, bgb.w);
        }
    };

    int nk = (K + 15) / 16;
    ldA(0);
    ldB(0);
    for (int t = 0; t < nk; t++) {
        int buf = t & 1;
        stA(buf);
        stB(buf);
        if (t + 1 < nk) { ldA((t + 1) * 16); ldB((t + 1) * 16); }
        __syncthreads();

        unsigned af[MT][4];
        #pragma unroll
        for (int mt = 0; mt < MT; mt++)
            ldmatrix_x4(af[mt][0], af[mt][1], af[mt][2], af[mt][3],
                        &Asm[buf][wm0 + mt * 16 + lm_row][lm_col]);
        unsigned bf[NT][2];
        #pragma unroll
        for (int nt = 0; nt < NT; nt++) {
            int n = wn0 + nt * 8 + lr;
            bf[nt][0] = *(const unsigned*)&Bs2[buf][lc][n];
            bf[nt][1] = *(const unsigned*)&Bs2[buf][lc + 4][n];
        }
        #pragma unroll
        for (int mt = 0; mt < MT; mt++)
            #pragma unroll
            for (int nt = 0; nt < NT; nt++)
                mma_f16(c[mt][nt][0], c[mt][nt][1], c[mt][nt][2], c[mt][nt][3],
                        af[mt][0], af[mt][1], af[mt][2], af[mt][3],
                        bf[nt][0], bf[nt][1]);
    }

    // ---- epilogue ----
    float asv[NT][2], adv[NT][2];
    if (EPI == 2) {
        #pragma unroll
        for (int nt = 0; nt < NT; nt++) {
            int gc = n0 + wn0 + nt * 8 + lc * 2;
            asv[nt][0] = a_src[gc]; asv[nt][1] = a_src[gc + 1];
            adv[nt][0] = a_dst[gc]; adv[nt][1] = a_dst[gc + 1];
        }
    }
    float* Cf = (float*)Cv;
    __half* Ch = (__half*)Cv;
    #pragma unroll
    for (int mt = 0; mt < MT; mt++) {
        int r0 = m0 + wm0 + mt * 16 + lr;
        int r1 = r0 + 8;
        float s0 = 0.f, s1 = 0.f, d0 = 0.f, d1 = 0.f;
        #pragma unroll
        for (int nt = 0; nt < NT; nt++) {
            int gc = n0 + wn0 + nt * 8 + lc * 2;
            float v0 = c[mt][nt][0], v1 = c[mt][nt][1];
            float v2 = c[mt][nt][2], v3 = c[mt][nt][3];
            if (EPI == 1 || EPI == 3) {
                float b0 = bias[gc], b1 = bias[gc + 1];
                v0 = selu_f(v0 + b0); v1 = selu_f(v1 + b1);
                v2 = selu_f(v2 + b0); v3 = selu_f(v3 + b1);
            }
            if (EPI == 2) {
                s0 += v0 * asv[nt][0] + v1 * asv[nt][1];
                s1 += v2 * asv[nt][0] + v3 * asv[nt][1];
                d0 += v0 * adv[nt][0] + v1 * adv[nt][1];
                d1 += v2 * adv[nt][0] + v3 * adv[nt][1];
            }
            if (EPI == 2 || EPI == 3) {
                if (r0 < M) *(__half2*)&Ch[(size_t)r0 * N + gc] = __floats2half2_rn(v0, v1);
                if (r1 < M) *(__half2*)&Ch[(size_t)r1 * N + gc] = __floats2half2_rn(v2, v3);
            } else {
                if (r0 < M) *(float2*)&Cf[(size_t)r0 * N + gc] = make_float2(v0, v1);
                if (r1 < M) *(float2*)&Cf[(size_t)r1 * N + gc] = make_float2(v2, v3);
            }
        }
        if (EPI == 2) {
            s0 += __shfl_xor_sync(0xFFFFFFFFu, s0, 1);
            s0 += __shfl_xor_sync(0xFFFFFFFFu, s0, 2);
            s1 += __shfl_xor_sync(0xFFFFFFFFu, s1, 1);
            s1 += __shfl_xor_sync(0xFFFFFFFFu, s1, 2);
            d0 += __shfl_xor_sync(0xFFFFFFFFu, d0, 1);
            d0 += __shfl_xor_sync(0xFFFFFFFFu, d0, 2);
            d1 += __shfl_xor_sync(0xFFFFFFFFu, d1, 1);
            d1 += __shfl_xor_sync(0xFFFFFFFFu, d1, 2);
            if (lc == 0) {
                int h = (n0 + wn0) >> 6;
                if (r0 < M) { atomicAdd(&AS[r0 * 4 + h], s0); atomicAdd(&AD[r0 * 4 + h], d0); }
                if (r1 < M) { atomicAdd(&AS[r1 * 4 + h], s1); atomicAdd(&AD[r1 * 4 + h], d1); }
            }
        }
    }
}

// =================== GAT gather: warp per dst, 4-edge unroll (R14 proven) ===================
__device__ __forceinline__ void ons_update(float e, const float* v,
                                           float& m, float& s, float* acc) {
    if (e <= m) {
        float w = __expf(e - m);
        s += w;
        #pragma unroll
        for (int q = 0; q < 8; q++) acc[q] += w * v[q];
    } else {
        float sc = __expf(m - e);   // first iter: exp(-inf)=0
        s = s * sc + 1.f;
        #pragma unroll
        for (int q = 0; q < 8; q++) acc[q] = acc[q] * sc + v[q];
        m = e;
    }
}
__device__ __forceinline__ void unpack8(uint4 u, float* v) {
    __half2* hh = (__half2*)&u;
    #pragma unroll
    for (int q = 0; q < 4; q++) {
        float2 f = __half22float2(hh[q]);
        v[q * 2] = f.x; v[q * 2 + 1] = f.y;
    }
}

__global__ void gat_gather_kernel(const int* __restrict__ rowptr, const int* __restrict__ adj,
                                  const __half* __restrict__ H, const float* __restrict__ AS,
                                  const float* __restrict__ AD, const float* __restrict__ gb,
                                  __half* __restrict__ OUT, int N) {
    int gw = (blockIdx.x * blockDim.x + threadIdx.x) >> 5;
    int lane = threadIdx.x & 31;
    if (gw >= N) return;
    int dst = gw;
    int h = lane >> 3;
    float adh = AD[dst * 4 + h];
    int beg = rowptr[dst], end = rowptr[dst + 1];
    float acc[8] = {};
    float m = -INFINITY, s = 0.f;
    int i = beg;
    for (; i + 4 <= end; i += 4) {
        int s0 = adj[i], s1 = adj[i + 1], s2 = adj[i + 2], s3 = adj[i + 3];
        float e0 = AS[s0 * 4 + h], e1 = AS[s1 * 4 + h];
        float e2 = AS[s2 * 4 + h], e3 = AS[s3 * 4 + h];
        uint4 u0 = *((const uint4*)(H + (size_t)s0 * 256) + lane);
        uint4 u1 = *((const uint4*)(H + (size_t)s1 * 256) + lane);
        uint4 u2 = *((const uint4*)(H + (size_t)s2 * 256) + lane);
        uint4 u3 = *((const uint4*)(H + (size_t)s3 * 256) + lane);
        e0 += adh; e1 += adh; e2 += adh; e3 += adh;
        e0 = e0 > 0.f ? e0 : 0.2f * e0;
        e1 = e1 > 0.f ? e1 : 0.2f * e1;
        e2 = e2 > 0.f ? e2 : 0.2f * e2;
        e3 = e3 > 0.f ? e3 : 0.2f * e3;
        float v[8];
        unpack8(u0, v); ons_update(e0, v, m, s, acc);
        unpack8(u1, v); ons_update(e1, v, m, s, acc);
        unpack8(u2, v); ons_update(e2, v, m, s, acc);
        unpack8(u3, v); ons_update(e3, v, m, s, acc);
    }
    for (; i < end; i++) {
        int s0 = adj[i];
        float e0 = AS[s0 * 4 + h] + adh;
        uint4 u0 = *((const uint4*)(H + (size_t)s0 * 256) + lane);
        float v[8];
        unpack8(u0, v);
        e0 = e0 > 0.f ? e0 : 0.2f * e0;
        ons_update(e0, v, m, s, acc);
    }
    float inv = 1.f / (s + 1e-16f);
    const float* gbp = gb + lane * 8;
    uint4 o;
    __half2* oh = (__half2*)&o;
    #pragma unroll
    for (int q = 0; q < 4; q++)
        oh[q] = __floats2half2_rn(acc[2 * q] * inv + gbp[2 * q],
                                  acc[2 * q + 1] * inv + gbp[2 * q + 1]);
    *((uint4*)(OUT + (size_t)dst * 256) + lane) = o;
}

// =================== standalone pool acc (fp16 input) ===================
__global__ void pool_acc_kernel(const __half* __restrict__ Hx, const int* __restrict__ batch,
                                float* __restrict__ SUMP, int* __restrict__ MAXP,
                                int* __restrict__ CNT, int N) {
    int c = threadIdx.x & 63;
    int r = blockIdx.x * 128 + (threadIdx.x >> 6);
    int rend = blockIdx.x * 128 + 128;
    if (rend > N) rend = N;
    float sum = 0.f, mx = -INFINITY;
    int cnt = 0, curg = -1;
    for (; r < rend; r += 4) {
        int g = batch[r];
        float v = __half2float(Hx[(size_t)r * 64 + c]);
        if (g != curg) {
            if (curg >= 0) {
                atomicAdd(&SUMP[curg * 64 + c], sum);
                atomicMax(&MAXP[curg * 64 + c], fmap(mx));
                if (c == 0) atomicAdd(&CNT[curg], cnt);
            }
            curg = g; sum = 0.f; mx = -INFINITY; cnt = 0;
        }
        sum += v;
        mx = fmaxf(mx, v);
        cnt++;
    }
    if (curg >= 0) {
        atomicAdd(&SUMP[curg * 64 + c], sum);
        atomicMax(&MAXP[curg * 64 + c], fmap(mx));
        if (c == 0) atomicAdd(&CNT[curg], cnt);
    }
}

// =================== final MLP head (pool_fin fused in) ===================
__global__ void mlp_kernel(const float* __restrict__ SUMP1, const int* __restrict__ MAXP1,
                           const int* __restrict__ CNT1,
                           const float* __restrict__ SUMP2, const int* __restrict__ MAXP2,
                           const int* __restrict__ CNT2,
                           const float* __restrict__ sum_w, const float* __restrict__ sum_b,
                           const float* __restrict__ sh1_w, const float* __restrict__ sh1_b,
                           const float* __restrict__ sh2_w, const float* __restrict__ sh2_b,
                           const float* __restrict__ sh3_w, const float* __restrict__ sh3_b,
                           const float* __restrict__ reg_w, const float* __restrict__ reg_b,
                           float* __restrict__ out) {
    __shared__ float zin[256], z1[128], z2[64], z3[64];
    int g = blockIdx.x, t = threadIdx.x;  // 128 threads
    if (t < 64) {
        float c1 = (float)CNT1[g]; if (c1 < 1.f) c1 = 1.f;
        float c2 = (float)CNT2[g]; if (c2 < 1.f) c2 = 1.f;
        zin[t]        = SUMP1[g * 64 + t] / c1;
        zin[64 + t]   = funmap(MAXP1[g * 64 + t]);
        zin[128 + t]  = SUMP2[g * 64 + t] / c2;
        zin[192 + t]  = funmap(MAXP2[g * 64 + t]);
    }
    __syncthreads();
    {
        float acc = sum_b[t];
        for (int k = 0; k < 256; k++) acc += zin[k] * sum_w[k * 128 + t];
        z1[t] = acc;
    }
    __syncthreads();
    if (t < 64) {
        float acc = sh1_b[t];
        for (int k = 0; k < 128; k++) acc += z1[k] * sh1_w[k * 64 + t];
        z2[t] = selu_f(acc);
    }
    __syncthreads();
    if (t < 64) {
        float acc = sh2_b[t];
        for (int k = 0; k < 64; k++) acc += z2[k] * sh2_w[k * 64 + t];
        z3[t] = selu_f(acc);
    }
    __syncthreads();
    if (t < 64) {
        float acc = sh3_b[t];
        for (int k = 0; k < 64; k++) acc += z3[k] * sh3_w[k * 64 + t];
        z2[t] = selu_f(acc);
    }
    __syncthreads();
    if (t < 32) {
        float acc = reg_b[t];
        for (int k = 0; k < 64; k++) acc += z2[k] * reg_w[k * 32 + t];
        out[g * 32 + t] = acc;
    }
}

// =================== host orchestration ===================
extern "C" void kernel_launch(void* const* d_in, const int* in_sizes, int n_in,
                              void* d_out, int out_size) {
    const float* x       = (const float*)d_in[0];
    const int*   ei      = (const int*)d_in[1];
    const int*   batch   = (const int*)d_in[2];
    const float* gat1_w  = (const float*)d_in[3];
    const float* gat1_as = (const float*)d_in[4];
    const float* gat1_ad = (const float*)d_in[5];
    const float* gat1_b  = (const float*)d_in[6];
    const float* lin1_w  = (const float*)d_in[7];
    const float* lin1_b  = (const float*)d_in[8];
    const float* gat2_w  = (const float*)d_in[9];
    const float* gat2_as = (const float*)d_in[10];
    const float* gat2_ad = (const float*)d_in[11];
    const float* gat2_b  = (const float*)d_in[12];
    const float* lin2_w  = (const float*)d_in[13];
    const float* lin2_b  = (const float*)d_in[14];
    const float* sum_w   = (const float*)d_in[15];
    const float* sum_b   = (const float*)d_in[16];
    const float* sh1_w   = (const float*)d_in[17];
    const float* sh1_b   = (const float*)d_in[18];
    const float* sh2_w   = (const float*)d_in[19];
    const float* sh2_b   = (const float*)d_in[20];
    const float* sh3_w   = (const float*)d_in[21];
    const float* sh3_b   = (const float*)d_in[22];
    const float* reg_w   = (const float*)d_in[23];
    const float* reg_b   = (const float*)d_in[24];

    int N  = in_sizes[2];
    int E  = in_sizes[1] / 2;
    int K1 = in_sizes[0] / N;
    int ET = E + N;

    __half *H, *OUT, *H1, *H2;
    float *AS, *AD, *AS2, *AD2, *SUMP1, *SUMP2;
    int *deg, *rowptr, *cur, *adj, *bsum, *MAXP1, *CNT1, *MAXP2, *CNT2;
    cudaGetSymbolAddress((void**)&H, g_H);
    cudaGetSymbolAddress((void**)&OUT, g_OUT);
    cudaGetSymbolAddress((void**)&H1, g_H1);
    cudaGetSymbolAddress((void**)&H2, g_H2);
    cudaGetSymbolAddress((void**)&AS, g_AS);
    cudaGetSymbolAddress((void**)&AD, g_AD);
    cudaGetSymbolAddress((void**)&AS2, g_AS2);
    cudaGetSymbolAddress((void**)&AD2, g_AD2);
    cudaGetSymbolAddress((void**)&deg, g_deg);
    cudaGetSymbolAddress((void**)&rowptr, g_rowptr);
    cudaGetSymbolAddress((void**)&cur, g_cur);
    cudaGetSymbolAddress((void**)&adj, g_adj);
    cudaGetSymbolAddress((void**)&bsum, g_bsum);
    cudaGetSymbolAddress((void**)&SUMP1, g_SUMP1);
    cudaGetSymbolAddress((void**)&MAXP1, g_MAXP1);
    cudaGetSymbolAddress((void**)&CNT1, g_CNT1);
    cudaGetSymbolAddress((void**)&SUMP2, g_SUMP2);
    cudaGetSymbolAddress((void**)&MAXP2, g_MAXP2);
    cudaGetSymbolAddress((void**)&CNT2, g_CNT2);

    int nScanBlocks = (N + 2047) / 2048;
    int nyH = (N + 127) / 128;
    dim3 gH(2, nyH);
    dim3 gH2(3, nyH);
    dim3 gL(1, nyH);

    cudaStream_t s1;
    cudaStreamCreateWithFlags(&s1, cudaStreamNonBlocking);
    cudaEvent_t evFork, evCSR;
    cudaEventCreateWithFlags(&evFork, cudaEventDisableTiming);
    cudaEventCreateWithFlags(&evCSR, cudaEventDisableTiming);

    cudaEventRecord(evFork, 0);
    cudaStreamWaitEvent(s1, evFork, 0);

    // --- CSR branch (s1): deg/cur + AS2/AD2 + pool buffers, then build ---
    init_csr_kernel<<<(N * 4 + 255) / 256, 256, 0, s1>>>(deg, cur, AS2, AD2,
                                                         SUMP1, MAXP1, CNT1,
                                                         SUMP2, MAXP2, CNT2, N);
    deg_count_kernel<<<(E + 255) / 256, 256, 0, s1>>>(ei, deg, E);
    scan1_kernel<<<nScanBlocks, 256, 0, s1>>>(deg, rowptr, bsum, N);
    scan23_kernel<<<nScanBlocks, 256, 0, s1>>>(rowptr, bsum, N, ET);
    fill_kernel<<<(ET + 255) / 256, 256, 0, s1>>>(ei, rowptr, cur, adj, E, ET);
    cudaEventRecord(evCSR, s1);

    // --- main branch: AS/AD zero, then GEMM1 ---
    init_main_kernel<<<(N * 4 + 255) / 256, 256>>>(AS, AD, N);
    f16_gemm_kernel<128, 2, 4, 2, 0, 0><<<gH, 256>>>(
        x, gat1_w, nullptr, H, gat1_as, gat1_ad, AS, AD,
        nullptr, nullptr, nullptr, nullptr, nullptr, N, 256, K1, 0);

    cudaStreamWaitEvent(0, evCSR, 0);

    gat_gather_kernel<<<(N * 32 + 255) / 256, 256>>>(rowptr, adj, H, AS, AD, gat1_b, OUT, N);
    f16_gemm_kernel<64, 4, 2, 3, 0, 1><<<gL, 256>>>(
        OUT, lin1_w, lin1_b, H1, nullptr, nullptr, nullptr, nullptr,
        nullptr, nullptr, nullptr, nullptr, nullptr, N, 64, 256, 0);

    f16_gemm_kernel<128, 2, 4, 2, 2, 1><<<gH2, 256>>>(
        H1, gat2_w, nullptr, H, gat2_as, gat2_ad, AS2, AD2,
        H1, batch, SUMP1, MAXP1, CNT1, N, 256, 64, 0);

    gat_gather_kernel<<<(N * 32 + 255) / 256, 256>>>(rowptr, adj, H, AS2, AD2, gat2_b, OUT, N);
    f16_gemm_kernel<64, 4, 2, 3, 0, 1><<<gL, 256>>>(
        OUT, lin2_w, lin2_b, H2, nullptr, nullptr, nullptr, nullptr,
        nullptr, nullptr, nullptr, nullptr, nullptr, N, 64, 256, 0);

    pool_acc_kernel<<<nyH, 256>>>(H2, batch, SUMP2, MAXP2, CNT2, N);

    mlp_kernel<<<GMAX, 128>>>(SUMP1, MAXP1, CNT1, SUMP2, MAXP2, CNT2,
                              sum_w, sum_b, sh1_w, sh1_b, sh2_w, sh2_b,
                              sh3_w, sh3_b, reg_w, reg_b, (float*)d_out);
}